// round 3
// baseline (speedup 1.0000x reference)
#include <cuda_runtime.h>
#include <cuda_bf16.h>
#include <cstdint>
#include <math.h>

#define EMBD 1536
#define HID 1536
#define VOCAB 32000
#define NLAYERS 2
#define SEQ 64
#define BATCH 32
#define NROW (SEQ*BATCH)          /* 2048 */
#define BH (BATCH*HID)            /* 49152 */

// ---------------- scratch (device globals; no allocation allowed) ----------------
__device__ __align__(16) float g_x0[(size_t)NROW*EMBD];      // emb * sqrt(EMB)
__device__ __align__(16) float g_l0x[3*(size_t)NROW*HID];    // layer0 x-side projections (r,u,c)
__device__ __align__(16) float g_X[(size_t)NROW*HID];        // layer-1 outputs per (t,b)
__device__ __align__(16) float g_h[NLAYERS*BH];              // hidden state
__device__ __align__(16) float g_pre[6*BH];                  // gate pre-activations

struct P {
  const int* tok; const float* hidden; const float* emb;
  const float *Wir,*bir,*Whr,*bhr,*Wiu,*biu,*Whu,*bhu,*Wic,*bic,*Whc,*bhc,*Wout,*bout;
};

__device__ __forceinline__ float tf32_rna(float v){
  uint32_t r; asm("cvt.rna.tf32.f32 %0, %1;" : "=r"(r) : "f"(v));
  return __uint_as_float(r);
}
__device__ __forceinline__ void mma_tf32(float c[4],
    uint32_t a0,uint32_t a1,uint32_t a2,uint32_t a3, uint32_t b0,uint32_t b1){
  asm volatile(
    "mma.sync.aligned.m16n8k8.row.col.f32.tf32.tf32.f32 "
    "{%0,%1,%2,%3},{%4,%5,%6,%7},{%8,%9},{%0,%1,%2,%3};"
    : "+f"(c[0]),"+f"(c[1]),"+f"(c[2]),"+f"(c[3])
    : "r"(a0),"r"(a1),"r"(a2),"r"(a3),"r"(b0),"r"(b1));
}
__device__ __forceinline__ float sigf(float x){ return 1.f/(1.f+expf(-x)); }

// ---------------- embed + scale ----------------
__global__ void embed_kernel(P p){
  int idx = blockIdx.x*blockDim.x + threadIdx.x;
  if (idx >= NROW*(EMBD/4)) return;
  int row = idx/(EMBD/4), e4 = idx%(EMBD/4);
  int tk = p.tok[row];
  float4 v = ((const float4*)p.emb)[(size_t)tk*(EMBD/4)+e4];
  float s = sqrtf((float)EMBD);
  v.x*=s; v.y*=s; v.z*=s; v.w*=s;
  ((float4*)g_x0)[(size_t)row*(EMBD/4)+e4] = v;
}
__global__ void init_h_kernel(P p){
  int i = blockIdx.x*blockDim.x + threadIdx.x;
  if (i < NLAYERS*BH) g_h[i] = p.hidden[i];
}
__global__ void copy_h_kernel(float* out){
  int i = blockIdx.x*blockDim.x + threadIdx.x;
  if (i < NLAYERS*BH) out[i] = g_h[i];
}

// ---------------- big GEMM (3xTF32): C[2048,N] = A[2048,1536] @ W[1536,N] (+bias) ----------------
__global__ __launch_bounds__(256) void big_gemm(
    const float* __restrict__ A, const float* __restrict__ W,
    float* __restrict__ C, const float* __restrict__ bias, int N)
{
  const int BK = 16;
  __shared__ float As[2][128][BK+4];
  __shared__ float Ws[2][BK][128+8];

  int tid = threadIdx.x;
  int warp = tid>>5, lane = tid&31;
  int gid = lane>>2, tig = lane&3;
  int wr = warp>>1, wc = warp&1;
  int m0 = blockIdx.y*128, n0 = blockIdx.x*128;

  float acc[2][8][4];
  #pragma unroll
  for (int a=0;a<2;a++)
    #pragma unroll
    for (int b=0;b<8;b++)
      #pragma unroll
      for (int cc=0;cc<4;cc++) acc[a][b][cc]=0.f;

  for (int kc=0; kc<HID; kc+=BK){
    #pragma unroll
    for (int i=0;i<2;i++){
      int q = tid + i*256;                      // 512 float4s of A (128x16)
      int m = q>>2, k4 = q&3;
      float4 v = *(const float4*)(A + (size_t)(m0+m)*HID + kc + k4*4);
      float vv[4] = {v.x,v.y,v.z,v.w};
      #pragma unroll
      for (int j=0;j<4;j++){
        float h = tf32_rna(vv[j]);
        As[0][m][k4*4+j] = h;
        As[1][m][k4*4+j] = tf32_rna(vv[j]-h);
      }
    }
    #pragma unroll
    for (int i=0;i<2;i++){
      int q = tid + i*256;                      // 512 float4s of W (16x128)
      int k = q>>5, n4 = q&31;
      float4 v = *(const float4*)(W + (size_t)(kc+k)*N + n0 + n4*4);
      float vv[4] = {v.x,v.y,v.z,v.w};
      #pragma unroll
      for (int j=0;j<4;j++){
        float h = tf32_rna(vv[j]);
        Ws[0][k][n4*4+j] = h;
        Ws[1][k][n4*4+j] = tf32_rna(vv[j]-h);
      }
    }
    __syncthreads();
    #pragma unroll
    for (int ks=0; ks<BK/8; ks++){
      int kk = ks*8;
      uint32_t ah[2][4], al[2][4];
      #pragma unroll
      for (int mt=0; mt<2; mt++){
        int ar = wr*32 + mt*16 + gid;
        ah[mt][0]=__float_as_uint(As[0][ar  ][kk+tig  ]);
        ah[mt][1]=__float_as_uint(As[0][ar+8][kk+tig  ]);
        ah[mt][2]=__float_as_uint(As[0][ar  ][kk+tig+4]);
        ah[mt][3]=__float_as_uint(As[0][ar+8][kk+tig+4]);
        al[mt][0]=__float_as_uint(As[1][ar  ][kk+tig  ]);
        al[mt][1]=__float_as_uint(As[1][ar+8][kk+tig  ]);
        al[mt][2]=__float_as_uint(As[1][ar  ][kk+tig+4]);
        al[mt][3]=__float_as_uint(As[1][ar+8][kk+tig+4]);
      }
      #pragma unroll
      for (int nt=0; nt<8; nt++){
        int c = wc*64 + nt*8 + gid;
        uint32_t bh0=__float_as_uint(Ws[0][kk+tig  ][c]);
        uint32_t bh1=__float_as_uint(Ws[0][kk+tig+4][c]);
        uint32_t bl0=__float_as_uint(Ws[1][kk+tig  ][c]);
        uint32_t bl1=__float_as_uint(Ws[1][kk+tig+4][c]);
        #pragma unroll
        for (int mt=0; mt<2; mt++){
          mma_tf32(acc[mt][nt], al[mt][0],al[mt][1],al[mt][2],al[mt][3], bh0,bh1);
          mma_tf32(acc[mt][nt], ah[mt][0],ah[mt][1],ah[mt][2],ah[mt][3], bl0,bl1);
          mma_tf32(acc[mt][nt], ah[mt][0],ah[mt][1],ah[mt][2],ah[mt][3], bh0,bh1);
        }
      }
    }
    __syncthreads();
  }
  #pragma unroll
  for (int mt=0; mt<2; mt++){
    int r0 = m0 + wr*32 + mt*16 + gid;
    #pragma unroll
    for (int nt=0; nt<8; nt++){
      int col = n0 + wc*64 + nt*8 + tig*2;
      float b0 = bias ? bias[col]   : 0.f;
      float b1 = bias ? bias[col+1] : 0.f;
      C[(size_t)r0*N + col  ]     = acc[mt][nt][0] + b0;
      C[(size_t)r0*N + col+1]     = acc[mt][nt][1] + b1;
      C[(size_t)(r0+8)*N + col  ] = acc[mt][nt][2] + b0;
      C[(size_t)(r0+8)*N + col+1] = acc[mt][nt][3] + b1;
    }
  }
}

// ---------------- recurrent GEMM (3xTF32): out[32,1536] = A[32,1536] @ W[1536,1536] ----------------
// layer 0: jobs 0..2 = h0 @ W_h{r,u,c}[0] -> slots 3..5
// layer 1: jobs 0..2 = x @ W_i{r,u,c}[1] -> slots 0..2 ; jobs 3..5 = h1 @ W_h{r,u,c}[1] -> slots 3..5
__global__ __launch_bounds__(128) void rec_gemm(P p, int layer){
  __shared__ float Ah[32][36], Al[32][36];
  __shared__ float Wh[32][72], Wl[32][72];

  int job = blockIdx.y;
  int n0 = blockIdx.x*64;
  const float* A; const float* W; int slot;
  if (layer==0){
    A = g_h;
    W = (job==0? p.Whr : job==1? p.Whu : p.Whc);
    slot = 3+job;
  } else if (job<3){
    A = g_h;  // new layer-0 output feeds layer 1
    W = (job==0? p.Wir : job==1? p.Wiu : p.Wic) + (size_t)HID*HID;
    slot = job;
  } else {
    A = g_h + BH;
    int j2 = job-3;
    W = (j2==0? p.Whr : j2==1? p.Whu : p.Whc) + (size_t)HID*HID;
    slot = job;
  }
  float* out = g_pre + (size_t)slot*BH;

  int tid = threadIdx.x;
  int warp = tid>>5, lane = tid&31;
  int gid = lane>>2, tig = lane&3;
  int mh = warp&1;       // row half (16 rows each)
  int nq = warp>>1;      // col quarter (32 cols each)

  float acc[4][4];
  #pragma unroll
  for (int a=0;a<4;a++)
    #pragma unroll
    for (int b=0;b<4;b++) acc[a][b]=0.f;

  for (int kc=0; kc<HID; kc+=32){
    #pragma unroll
    for (int i=0;i<2;i++){
      int q = tid + i*128;                      // 256 float4s of A (32x32)
      int m = q>>3, k4 = q&7;
      float4 v = *(const float4*)(A + (size_t)m*HID + kc + k4*4);
      float vv[4] = {v.x,v.y,v.z,v.w};
      #pragma unroll
      for (int j=0;j<4;j++){
        float h = tf32_rna(vv[j]);
        Ah[m][k4*4+j] = h;
        Al[m][k4*4+j] = tf32_rna(vv[j]-h);
      }
    }
    #pragma unroll
    for (int i=0;i<4;i++){
      int q = tid + i*128;                      // 512 float4s of W (32x64)
      int k = q>>4, n4 = q&15;
      float4 v = *(const float4*)(W + (size_t)(kc+k)*HID + n0 + n4*4);
      float vv[4] = {v.x,v.y,v.z,v.w};
      #pragma unroll
      for (int j=0;j<4;j++){
        float h = tf32_rna(vv[j]);
        Wh[k][n4*4+j] = h;
        Wl[k][n4*4+j] = tf32_rna(vv[j]-h);
      }
    }
    __syncthreads();
    #pragma unroll
    for (int ks=0; ks<4; ks++){
      int kk = ks*8;
      int ar = mh*16 + gid;
      uint32_t ah0=__float_as_uint(Ah[ar  ][kk+tig  ]);
      uint32_t ah1=__float_as_uint(Ah[ar+8][kk+tig  ]);
      uint32_t ah2=__float_as_uint(Ah[ar  ][kk+tig+4]);
      uint32_t ah3=__float_as_uint(Ah[ar+8][kk+tig+4]);
      uint32_t al0=__float_as_uint(Al[ar  ][kk+tig  ]);
      uint32_t al1=__float_as_uint(Al[ar+8][kk+tig  ]);
      uint32_t al2=__float_as_uint(Al[ar  ][kk+tig+4]);
      uint32_t al3=__float_as_uint(Al[ar+8][kk+tig+4]);
      #pragma unroll
      for (int nt=0; nt<4; nt++){
        int c = nq*32 + nt*8 + gid;
        uint32_t bh0=__float_as_uint(Wh[kk+tig  ][c]);
        uint32_t bh1=__float_as_uint(Wh[kk+tig+4][c]);
        uint32_t bl0=__float_as_uint(Wl[kk+tig  ][c]);
        uint32_t bl1=__float_as_uint(Wl[kk+tig+4][c]);
        mma_tf32(acc[nt], al0,al1,al2,al3, bh0,bh1);
        mma_tf32(acc[nt], ah0,ah1,ah2,ah3, bl0,bl1);
        mma_tf32(acc[nt], ah0,ah1,ah2,ah3, bh0,bh1);
      }
    }
    __syncthreads();
  }
  #pragma unroll
  for (int nt=0; nt<4; nt++){
    int col = n0 + nq*32 + nt*8 + tig*2;
    int r0 = mh*16 + gid;
    out[(size_t)r0*HID + col  ]     = acc[nt][0];
    out[(size_t)r0*HID + col+1]     = acc[nt][1];
    out[(size_t)(r0+8)*HID + col  ] = acc[nt][2];
    out[(size_t)(r0+8)*HID + col+1] = acc[nt][3];
  }
}

// ---------------- pointwise gate math ----------------
__global__ void pointwise(P p, int t, int layer){
  int idx = blockIdx.x*blockDim.x + threadIdx.x;
  if (idx >= BH) return;
  int j = idx % HID;
  size_t row = (size_t)t*BATCH + (idx / HID);
  float xr,xu,xc;
  const float *bir,*biu,*bic,*bhr,*bhu,*bhc;
  if (layer==0){
    xr = g_l0x[0*(size_t)NROW*HID + row*HID + j];
    xu = g_l0x[1*(size_t)NROW*HID + row*HID + j];
    xc = g_l0x[2*(size_t)NROW*HID + row*HID + j];
    bir=p.bir; biu=p.biu; bic=p.bic; bhr=p.bhr; bhu=p.bhu; bhc=p.bhc;
  } else {
    xr = g_pre[0*BH + idx];
    xu = g_pre[1*BH + idx];
    xc = g_pre[2*BH + idx];
    bir=p.bir+HID; biu=p.biu+HID; bic=p.bic+HID; bhr=p.bhr+HID; bhu=p.bhu+HID; bhc=p.bhc+HID;
  }
  float hr = g_pre[3*BH + idx], hu = g_pre[4*BH + idx], hc = g_pre[5*BH + idx];
  float h  = g_h[layer*BH + idx];
  float r = sigf(xr + bir[j] + hr + bhr[j]);
  float u = sigf(xu + biu[j] + hu + bhu[j]);
  float c = tanhf(xc + bic[j] + r*(hc + bhc[j]));
  float hn = (1.f-u)*c + u*h;
  g_h[layer*BH + idx] = hn;
  if (layer==1) g_X[row*HID + j] = hn;
}

extern "C" void kernel_launch(void* const* d_in, const int* in_sizes, int n_in,
                              void* d_out, int out_size) {
  P p;
  p.tok = (const int*)  d_in[0];
  p.hidden = (const float*)d_in[1];
  p.emb = (const float*)d_in[2];
  p.Wir = (const float*)d_in[3];  p.bir = (const float*)d_in[4];
  p.Whr = (const float*)d_in[5];  p.bhr = (const float*)d_in[6];
  p.Wiu = (const float*)d_in[7];  p.biu = (const float*)d_in[8];
  p.Whu = (const float*)d_in[9];  p.bhu = (const float*)d_in[10];
  p.Wic = (const float*)d_in[11]; p.bic = (const float*)d_in[12];
  p.Whc = (const float*)d_in[13]; p.bhc = (const float*)d_in[14];
  p.Wout= (const float*)d_in[15]; p.bout= (const float*)d_in[16];
  float* out = (float*)d_out;

  float* x0;  cudaGetSymbolAddress((void**)&x0,  g_x0);
  float* l0x; cudaGetSymbolAddress((void**)&l0x, g_l0x);
  float* X;   cudaGetSymbolAddress((void**)&X,   g_X);

  init_h_kernel<<<(NLAYERS*BH+255)/256, 256>>>(p);
  embed_kernel<<<(NROW*(EMBD/4)+255)/256, 256>>>(p);

  // layer-0 x-side projections for all (t,b) at once (no bias; added in pointwise)
  big_gemm<<<dim3(HID/128, NROW/128), 256>>>(x0, p.Wir, l0x + 0*(size_t)NROW*HID, nullptr, HID);
  big_gemm<<<dim3(HID/128, NROW/128), 256>>>(x0, p.Wiu, l0x + 1*(size_t)NROW*HID, nullptr, HID);
  big_gemm<<<dim3(HID/128, NROW/128), 256>>>(x0, p.Wic, l0x + 2*(size_t)NROW*HID, nullptr, HID);

  for (int t=0; t<SEQ; t++){
    rec_gemm<<<dim3(HID/64, 3), 128>>>(p, 0);
    pointwise<<<(BH+255)/256, 256>>>(p, t, 0);
    rec_gemm<<<dim3(HID/64, 6), 128>>>(p, 1);
    pointwise<<<(BH+255)/256, 256>>>(p, t, 1);
  }

  // output projection for all steps at once: logits = X @ Wout + bout
  big_gemm<<<dim3(VOCAB/128, NROW/128), 256>>>(X, p.Wout, out, p.bout, VOCAB);

  // h_final after logits region
  copy_h_kernel<<<(NLAYERS*BH+255)/256, 256>>>(out + (size_t)SEQ*BATCH*VOCAB);
}

// round 4
// speedup vs baseline: 1.1841x; 1.1841x over previous
#include <cuda_runtime.h>
#include <cuda_bf16.h>
#include <cstdint>
#include <math.h>

#define EMBD 1536
#define HID 1536
#define VOCAB 32000
#define NLAYERS 2
#define SEQ 64
#define BATCH 32
#define NROW (SEQ*BATCH)          /* 2048 */
#define BH (BATCH*HID)            /* 49152 */

// ---------------- scratch (device globals; no allocation allowed) ----------------
__device__ __align__(16) float g_x0[(size_t)NROW*EMBD];      // emb * sqrt(EMB)
__device__ __align__(16) float g_l0x[3*(size_t)NROW*HID];    // layer0 x-side projections (r,u,c)
__device__ __align__(16) float g_X[(size_t)NROW*HID];        // layer-1 outputs per (t,b)
__device__ __align__(16) float g_hbuf[2][NLAYERS*BH];        // ping-pong hidden state
__device__ __align__(16) float g_pre[3*BH];                  // layer-1 h-side pre-activations

struct P {
  const int* tok; const float* hidden; const float* emb;
  const float *Wir,*bir,*Whr,*bhr,*Wiu,*biu,*Whu,*bhu,*Wic,*bic,*Whc,*bhc,*Wout,*bout;
};

__device__ __forceinline__ float tf32_rna(float v){
  uint32_t r; asm("cvt.rna.tf32.f32 %0, %1;" : "=r"(r) : "f"(v));
  return __uint_as_float(r);
}
__device__ __forceinline__ void mma_tf32(float c[4],
    uint32_t a0,uint32_t a1,uint32_t a2,uint32_t a3, uint32_t b0,uint32_t b1){
  asm volatile(
    "mma.sync.aligned.m16n8k8.row.col.f32.tf32.tf32.f32 "
    "{%0,%1,%2,%3},{%4,%5,%6,%7},{%8,%9},{%0,%1,%2,%3};"
    : "+f"(c[0]),"+f"(c[1]),"+f"(c[2]),"+f"(c[3])
    : "r"(a0),"r"(a1),"r"(a2),"r"(a3),"r"(b0),"r"(b1));
}
__device__ __forceinline__ float sigf(float x){ return 1.f/(1.f+expf(-x)); }

// ---------------- embed + scale ----------------
__global__ void embed_kernel(P p){
  int idx = blockIdx.x*blockDim.x + threadIdx.x;
  if (idx >= NROW*(EMBD/4)) return;
  int row = idx/(EMBD/4), e4 = idx%(EMBD/4);
  int tk = p.tok[row];
  float4 v = ((const float4*)p.emb)[(size_t)tk*(EMBD/4)+e4];
  float s = sqrtf((float)EMBD);
  v.x*=s; v.y*=s; v.z*=s; v.w*=s;
  ((float4*)g_x0)[(size_t)row*(EMBD/4)+e4] = v;
}
__global__ void init_h_kernel(P p){
  int i = blockIdx.x*blockDim.x + threadIdx.x;
  if (i < NLAYERS*BH) g_hbuf[0][i] = p.hidden[i];
}
__global__ void copy_h_kernel(float* out){
  int i = blockIdx.x*blockDim.x + threadIdx.x;
  if (i < NLAYERS*BH) out[i] = g_hbuf[0][i];
}

// ---------------- big GEMM: C[2048,N] = A[2048,1536] @ W[1536,N] (+bias) ----------------
// PASSES=3 -> 3xTF32 (fp32-accurate); PASSES=1 -> single TF32 pass.
// Register-prefetch double buffering: LDGs for chunk k+1 issue before compute of chunk k.
template<int PASSES>
__global__ __launch_bounds__(256) void big_gemm(
    const float* __restrict__ A, const float* __restrict__ W,
    float* __restrict__ C, const float* __restrict__ bias, int N)
{
  constexpr int BK = 16;
  constexpr int SPL = (PASSES>1) ? 2 : 1;
  __shared__ float As[SPL][128][BK+4];
  __shared__ float Ws[SPL][BK][128+8];

  int tid = threadIdx.x;
  int warp = tid>>5, lane = tid&31;
  int gid = lane>>2, tig = lane&3;
  int wr = warp>>1, wc = warp&1;
  int m0 = blockIdx.y*128, n0 = blockIdx.x*128;

  float acc[2][8][4];
  #pragma unroll
  for (int a=0;a<2;a++)
    #pragma unroll
    for (int b=0;b<8;b++)
      #pragma unroll
      for (int cc=0;cc<4;cc++) acc[a][b][cc]=0.f;

  float4 ra[2], rw[2];
  auto loadA = [&](int kc){
    #pragma unroll
    for (int i=0;i<2;i++){
      int q = tid + i*256; int m = q>>2, k4 = q&3;
      ra[i] = *(const float4*)(A + (size_t)(m0+m)*HID + kc + k4*4);
    }
  };
  auto loadW = [&](int kc){
    #pragma unroll
    for (int i=0;i<2;i++){
      int q = tid + i*256; int k = q>>5, n4 = q&31;
      rw[i] = *(const float4*)(W + (size_t)(kc+k)*N + n0 + n4*4);
    }
  };
  loadA(0); loadW(0);

  for (int kc=0; kc<HID; kc+=BK){
    // store staged regs -> smem (with tf32 hi/lo split)
    #pragma unroll
    for (int i=0;i<2;i++){
      int q = tid + i*256; int m = q>>2, k4 = q&3;
      float vv[4] = {ra[i].x,ra[i].y,ra[i].z,ra[i].w};
      #pragma unroll
      for (int j=0;j<4;j++){
        float h = tf32_rna(vv[j]);
        As[0][m][k4*4+j] = h;
        if constexpr (PASSES>1) As[1][m][k4*4+j] = tf32_rna(vv[j]-h);
      }
    }
    #pragma unroll
    for (int i=0;i<2;i++){
      int q = tid + i*256; int k = q>>5, n4 = q&31;
      float vv[4] = {rw[i].x,rw[i].y,rw[i].z,rw[i].w};
      #pragma unroll
      for (int j=0;j<4;j++){
        float h = tf32_rna(vv[j]);
        Ws[0][k][n4*4+j] = h;
        if constexpr (PASSES>1) Ws[1][k][n4*4+j] = tf32_rna(vv[j]-h);
      }
    }
    __syncthreads();
    if (kc+BK < HID){ loadA(kc+BK); loadW(kc+BK); }  // prefetch next chunk

    #pragma unroll
    for (int ks=0; ks<BK/8; ks++){
      int kk = ks*8;
      uint32_t ah[2][4], al[2][4];
      #pragma unroll
      for (int mt=0; mt<2; mt++){
        int ar = wr*32 + mt*16 + gid;
        ah[mt][0]=__float_as_uint(As[0][ar  ][kk+tig  ]);
        ah[mt][1]=__float_as_uint(As[0][ar+8][kk+tig  ]);
        ah[mt][2]=__float_as_uint(As[0][ar  ][kk+tig+4]);
        ah[mt][3]=__float_as_uint(As[0][ar+8][kk+tig+4]);
        if constexpr (PASSES>1){
          al[mt][0]=__float_as_uint(As[1][ar  ][kk+tig  ]);
          al[mt][1]=__float_as_uint(As[1][ar+8][kk+tig  ]);
          al[mt][2]=__float_as_uint(As[1][ar  ][kk+tig+4]);
          al[mt][3]=__float_as_uint(As[1][ar+8][kk+tig+4]);
        }
      }
      #pragma unroll
      for (int nt=0; nt<8; nt++){
        int c = wc*64 + nt*8 + gid;
        uint32_t bh0=__float_as_uint(Ws[0][kk+tig  ][c]);
        uint32_t bh1=__float_as_uint(Ws[0][kk+tig+4][c]);
        #pragma unroll
        for (int mt=0; mt<2; mt++){
          if constexpr (PASSES>1){
            uint32_t bl0=__float_as_uint(Ws[1][kk+tig  ][c]);
            uint32_t bl1=__float_as_uint(Ws[1][kk+tig+4][c]);
            mma_tf32(acc[mt][nt], al[mt][0],al[mt][1],al[mt][2],al[mt][3], bh0,bh1);
            mma_tf32(acc[mt][nt], ah[mt][0],ah[mt][1],ah[mt][2],ah[mt][3], bl0,bl1);
          }
          mma_tf32(acc[mt][nt], ah[mt][0],ah[mt][1],ah[mt][2],ah[mt][3], bh0,bh1);
        }
      }
    }
    __syncthreads();
  }
  #pragma unroll
  for (int mt=0; mt<2; mt++){
    int r0 = m0 + wr*32 + mt*16 + gid;
    #pragma unroll
    for (int nt=0; nt<8; nt++){
      int col = n0 + wc*64 + nt*8 + tig*2;
      float b0 = bias ? bias[col]   : 0.f;
      float b1 = bias ? bias[col+1] : 0.f;
      C[(size_t)r0*N + col  ]     = acc[mt][nt][0] + b0;
      C[(size_t)r0*N + col+1]     = acc[mt][nt][1] + b1;
      C[(size_t)(r0+8)*N + col  ] = acc[mt][nt][2] + b0;
      C[(size_t)(r0+8)*N + col+1] = acc[mt][nt][3] + b1;
    }
  }
}

// ---------------- recurrent GEMM core: acc[job][mt] = A[32,1536] @ Wj[1536, n0:n0+32], 3xTF32 ----
// Block = 128 threads (4 warps). Warp w owns cols n0+w*8..+7 for ALL 3 jobs, so each
// thread ends up holding r/u/c fragments for the SAME elements -> gate math fuses in-register.
__device__ __forceinline__ void rec_core(
    const float* __restrict__ A,
    const float* __restrict__ W0, const float* __restrict__ W1, const float* __restrict__ W2,
    int n0, float acc[3][2][4])
{
  __shared__ float As[2][32][36];         // [hi/lo][m][k]
  __shared__ float Ws[3][2][32][36];      // [job][hi/lo][k][n]
  const float* Wp[3] = {W0, W1, W2};

  int tid = threadIdx.x, warp = tid>>5, lane = tid&31;
  int gid = lane>>2, tig = lane&3;

  #pragma unroll
  for (int j=0;j<3;j++)
    #pragma unroll
    for (int mt=0;mt<2;mt++)
      #pragma unroll
      for (int f=0;f<4;f++) acc[j][mt][f]=0.f;

  float4 ra[2], rwreg[3][2];
  auto loadA = [&](int kc){
    #pragma unroll
    for (int i=0;i<2;i++){
      int q = tid + i*128; int m = q>>3, k4 = q&7;
      ra[i] = *(const float4*)(A + (size_t)m*HID + kc + k4*4);
    }
  };
  auto loadW = [&](int kc){
    #pragma unroll
    for (int j=0;j<3;j++)
      #pragma unroll
      for (int i=0;i<2;i++){
        int q = tid + i*128; int k = q>>3, n4 = q&7;
        rwreg[j][i] = *(const float4*)(Wp[j] + (size_t)(kc+k)*HID + n0 + n4*4);
      }
  };
  loadA(0); loadW(0);

  for (int kc=0; kc<HID; kc+=32){
    #pragma unroll
    for (int i=0;i<2;i++){
      int q = tid + i*128; int m = q>>3, k4 = q&7;
      float vv[4] = {ra[i].x,ra[i].y,ra[i].z,ra[i].w};
      #pragma unroll
      for (int j=0;j<4;j++){
        float h = tf32_rna(vv[j]);
        As[0][m][k4*4+j] = h;
        As[1][m][k4*4+j] = tf32_rna(vv[j]-h);
      }
    }
    #pragma unroll
    for (int j=0;j<3;j++)
      #pragma unroll
      for (int i=0;i<2;i++){
        int q = tid + i*128; int k = q>>3, n4 = q&7;
        float vv[4] = {rwreg[j][i].x,rwreg[j][i].y,rwreg[j][i].z,rwreg[j][i].w};
        #pragma unroll
        for (int jj=0;jj<4;jj++){
          float h = tf32_rna(vv[jj]);
          Ws[j][0][k][n4*4+jj] = h;
          Ws[j][1][k][n4*4+jj] = tf32_rna(vv[jj]-h);
        }
      }
    __syncthreads();
    if (kc+32 < HID){ loadA(kc+32); loadW(kc+32); }   // prefetch next chunk

    #pragma unroll
    for (int ks=0; ks<4; ks++){
      int kk = ks*8;
      uint32_t ah[2][4], al[2][4];
      #pragma unroll
      for (int mt=0; mt<2; mt++){
        int ar = mt*16 + gid;
        ah[mt][0]=__float_as_uint(As[0][ar  ][kk+tig  ]);
        ah[mt][1]=__float_as_uint(As[0][ar+8][kk+tig  ]);
        ah[mt][2]=__float_as_uint(As[0][ar  ][kk+tig+4]);
        ah[mt][3]=__float_as_uint(As[0][ar+8][kk+tig+4]);
        al[mt][0]=__float_as_uint(As[1][ar  ][kk+tig  ]);
        al[mt][1]=__float_as_uint(As[1][ar+8][kk+tig  ]);
        al[mt][2]=__float_as_uint(As[1][ar  ][kk+tig+4]);
        al[mt][3]=__float_as_uint(As[1][ar+8][kk+tig+4]);
      }
      int c = warp*8 + gid;
      #pragma unroll
      for (int j=0;j<3;j++){
        uint32_t bh0=__float_as_uint(Ws[j][0][kk+tig  ][c]);
        uint32_t bh1=__float_as_uint(Ws[j][0][kk+tig+4][c]);
        uint32_t bl0=__float_as_uint(Ws[j][1][kk+tig  ][c]);
        uint32_t bl1=__float_as_uint(Ws[j][1][kk+tig+4][c]);
        #pragma unroll
        for (int mt=0; mt<2; mt++){
          mma_tf32(acc[j][mt], al[mt][0],al[mt][1],al[mt][2],al[mt][3], bh0,bh1);
          mma_tf32(acc[j][mt], ah[mt][0],ah[mt][1],ah[mt][2],ah[mt][3], bl0,bl1);
          mma_tf32(acc[j][mt], ah[mt][0],ah[mt][1],ah[mt][2],ah[mt][3], bh0,bh1);
        }
      }
    }
    __syncthreads();
  }
}

// ---- step kernel 1: both layers' h-side GEMMs (parallel); layer-0 gates fused ----
__global__ __launch_bounds__(128) void rec_step1(P p, int t,
    const float* __restrict__ cur, float* __restrict__ nxt)
{
  int layer = blockIdx.y;
  int n0 = blockIdx.x*32;
  size_t off = (layer==1) ? (size_t)HID*HID : 0;
  const float* A = cur + (size_t)layer*BH;
  float acc[3][2][4];
  rec_core(A, p.Whr+off, p.Whu+off, p.Whc+off, n0, acc);

  int lane = threadIdx.x&31, warp = threadIdx.x>>5;
  int gid = lane>>2, tig = lane&3;

  if (layer==1){
    #pragma unroll
    for (int j=0;j<3;j++)
      #pragma unroll
      for (int mt=0;mt<2;mt++){
        int r = mt*16 + gid;
        int cc = n0 + warp*8 + tig*2;
        g_pre[(size_t)j*BH + (size_t)r*HID + cc  ]     = acc[j][mt][0];
        g_pre[(size_t)j*BH + (size_t)r*HID + cc+1]     = acc[j][mt][1];
        g_pre[(size_t)j*BH + (size_t)(r+8)*HID + cc  ] = acc[j][mt][2];
        g_pre[(size_t)j*BH + (size_t)(r+8)*HID + cc+1] = acc[j][mt][3];
      }
  } else {
    #pragma unroll
    for (int mt=0;mt<2;mt++)
      #pragma unroll
      for (int f=0;f<4;f++){
        int r  = mt*16 + gid + ((f>=2)?8:0);
        int cc = n0 + warp*8 + tig*2 + (f&1);
        size_t trow = (size_t)t*BATCH + r;
        float xr = g_l0x[0*(size_t)NROW*HID + trow*HID + cc];
        float xu = g_l0x[1*(size_t)NROW*HID + trow*HID + cc];
        float xc = g_l0x[2*(size_t)NROW*HID + trow*HID + cc];
        float rr = sigf(xr + p.bir[cc] + acc[0][mt][f] + p.bhr[cc]);
        float uu = sigf(xu + p.biu[cc] + acc[1][mt][f] + p.bhu[cc]);
        float cv = tanhf(xc + p.bic[cc] + rr*(acc[2][mt][f] + p.bhc[cc]));
        float h  = cur[(size_t)r*HID + cc];
        nxt[(size_t)r*HID + cc] = (1.f-uu)*cv + uu*h;
      }
  }
}

// ---- step kernel 2: layer-1 x-side GEMMs (A = fresh h0) + layer-1 gates fused ----
__global__ __launch_bounds__(128) void rec_step2(P p, int t,
    const float* __restrict__ cur, float* __restrict__ nxt)
{
  int n0 = blockIdx.x*32;
  size_t off = (size_t)HID*HID;
  float acc[3][2][4];
  rec_core(nxt /* h0_new */, p.Wir+off, p.Wiu+off, p.Wic+off, n0, acc);

  int lane = threadIdx.x&31, warp = threadIdx.x>>5;
  int gid = lane>>2, tig = lane&3;

  #pragma unroll
  for (int mt=0;mt<2;mt++)
    #pragma unroll
    for (int f=0;f<4;f++){
      int r  = mt*16 + gid + ((f>=2)?8:0);
      int cc = n0 + warp*8 + tig*2 + (f&1);
      float hr = g_pre[0*(size_t)BH + (size_t)r*HID + cc];
      float hu = g_pre[1*(size_t)BH + (size_t)r*HID + cc];
      float hc = g_pre[2*(size_t)BH + (size_t)r*HID + cc];
      float rr = sigf(acc[0][mt][f] + p.bir[HID+cc] + hr + p.bhr[HID+cc]);
      float uu = sigf(acc[1][mt][f] + p.biu[HID+cc] + hu + p.bhu[HID+cc]);
      float cv = tanhf(acc[2][mt][f] + p.bic[HID+cc] + rr*(hc + p.bhc[HID+cc]));
      float h  = cur[BH + (size_t)r*HID + cc];
      float hn = (1.f-uu)*cv + uu*h;
      nxt[BH + (size_t)r*HID + cc] = hn;
      g_X[((size_t)t*BATCH + r)*HID + cc] = hn;
    }
}

extern "C" void kernel_launch(void* const* d_in, const int* in_sizes, int n_in,
                              void* d_out, int out_size) {
  P p;
  p.tok = (const int*)  d_in[0];
  p.hidden = (const float*)d_in[1];
  p.emb = (const float*)d_in[2];
  p.Wir = (const float*)d_in[3];  p.bir = (const float*)d_in[4];
  p.Whr = (const float*)d_in[5];  p.bhr = (const float*)d_in[6];
  p.Wiu = (const float*)d_in[7];  p.biu = (const float*)d_in[8];
  p.Whu = (const float*)d_in[9];  p.bhu = (const float*)d_in[10];
  p.Wic = (const float*)d_in[11]; p.bic = (const float*)d_in[12];
  p.Whc = (const float*)d_in[13]; p.bhc = (const float*)d_in[14];
  p.Wout= (const float*)d_in[15]; p.bout= (const float*)d_in[16];
  float* out = (float*)d_out;

  float* x0;  cudaGetSymbolAddress((void**)&x0,  g_x0);
  float* l0x; cudaGetSymbolAddress((void**)&l0x, g_l0x);
  float* X;   cudaGetSymbolAddress((void**)&X,   g_X);
  float* hb;  cudaGetSymbolAddress((void**)&hb,  g_hbuf);

  init_h_kernel<<<(NLAYERS*BH+255)/256, 256>>>(p);
  embed_kernel<<<(NROW*(EMBD/4)+255)/256, 256>>>(p);

  // layer-0 x-side projections for all (t,b) at once (3xTF32; feeds recurrence)
  big_gemm<3><<<dim3(HID/128, NROW/128), 256>>>(x0, p.Wir, l0x + 0*(size_t)NROW*HID, nullptr, HID);
  big_gemm<3><<<dim3(HID/128, NROW/128), 256>>>(x0, p.Wiu, l0x + 1*(size_t)NROW*HID, nullptr, HID);
  big_gemm<3><<<dim3(HID/128, NROW/128), 256>>>(x0, p.Wic, l0x + 2*(size_t)NROW*HID, nullptr, HID);

  for (int t=0; t<SEQ; t++){
    const float* cur = hb + (size_t)(t&1)*NLAYERS*BH;
    float*       nxt = hb + (size_t)((t+1)&1)*NLAYERS*BH;
    rec_step1<<<dim3(HID/32, 2), 128>>>(p, t, cur, nxt);
    rec_step2<<<dim3(HID/32),    128>>>(p, t, cur, nxt);
  }

  // output projection for all steps at once (single-pass TF32): logits = X @ Wout + bout
  big_gemm<1><<<dim3(VOCAB/128, NROW/128), 256>>>(X, p.Wout, out, p.bout, VOCAB);

  // h_final after logits region (after 64 steps, state is back in buffer 0)
  copy_h_kernel<<<(NLAYERS*BH+255)/256, 256>>>(out + (size_t)SEQ*BATCH*VOCAB);
}

// round 5
// speedup vs baseline: 1.7866x; 1.5089x over previous
#include <cuda_runtime.h>
#include <cuda_bf16.h>
#include <cstdint>
#include <math.h>

#define EMBD 1536
#define HID 1536
#define KH (HID/2)                /* 768 packed k-pairs */
#define VOCAB 32000
#define NLAYERS 2
#define SEQ 64
#define BATCH 32
#define NROW (SEQ*BATCH)          /* 2048 */
#define BH (BATCH*HID)            /* 49152 */

// ---------------- device scratch (no allocation allowed) ----------------
__device__ uint32_t g_wsp[12][2][HID][KH];            // pre-split weights: [mat][hi/lo][n][k2] packed bf16x2
__device__ uint32_t g_x0sp[2][NROW][KH];              // split scaled embeddings
__device__ uint32_t g_hsp[2][NLAYERS][2][BATCH][KH];  // split hidden state (ping-pong)
__device__ float    g_hbuf[2][NLAYERS*BH];            // fp32 hidden state (ping-pong)
__device__ float    g_l0x[3*(size_t)NROW*HID];        // layer0 x-side projections
__device__ float    g_X[(size_t)NROW*HID];            // layer1 outputs (feeds out GEMM)
__device__ float    g_pre[3*(size_t)BH];              // layer1 h-side pre-activations

struct P {
  const int* tok; const float* hidden; const float* emb;
  const float *Wir,*bir,*Whr,*bhr,*Wiu,*biu,*Whu,*bhu,*Wic,*bic,*Whc,*bhc,*Wout,*bout;
};

__device__ __forceinline__ float sigf(float x){ return 1.f/(1.f+expf(-x)); }

__device__ __forceinline__ uint32_t packbf(float a, float b){
  __nv_bfloat162 t; t.x = __float2bfloat16_rn(a); t.y = __float2bfloat16_rn(b);
  return *reinterpret_cast<uint32_t*>(&t);
}
__device__ __forceinline__ void split2(float a, float b, uint32_t& hi, uint32_t& lo){
  __nv_bfloat16 ha = __float2bfloat16_rn(a), hb = __float2bfloat16_rn(b);
  float ra = a - __bfloat162float(ha), rb = b - __bfloat162float(hb);
  hi = packbf(__bfloat162float(ha), __bfloat162float(hb));
  lo = packbf(ra, rb);
}

__device__ __forceinline__ void mma_bf16(float c[4],
    uint32_t a0,uint32_t a1,uint32_t a2,uint32_t a3, uint32_t b0,uint32_t b1){
  asm volatile(
    "mma.sync.aligned.m16n8k16.row.col.f32.bf16.bf16.f32 "
    "{%0,%1,%2,%3},{%4,%5,%6,%7},{%8,%9},{%0,%1,%2,%3};"
    : "+f"(c[0]),"+f"(c[1]),"+f"(c[2]),"+f"(c[3])
    : "r"(a0),"r"(a1),"r"(a2),"r"(a3),"r"(b0),"r"(b1));
}
__device__ __forceinline__ void mma_tf32(float c[4],
    uint32_t a0,uint32_t a1,uint32_t a2,uint32_t a3, uint32_t b0,uint32_t b1){
  asm volatile(
    "mma.sync.aligned.m16n8k8.row.col.f32.tf32.tf32.f32 "
    "{%0,%1,%2,%3},{%4,%5,%6,%7},{%8,%9},{%0,%1,%2,%3};"
    : "+f"(c[0]),"+f"(c[1]),"+f"(c[2]),"+f"(c[3])
    : "r"(a0),"r"(a1),"r"(a2),"r"(a3),"r"(b0),"r"(b1));
}
__device__ __forceinline__ float tf32_rna(float v){
  uint32_t r; asm("cvt.rna.tf32.f32 %0, %1;" : "=r"(r) : "f"(v));
  return __uint_as_float(r);
}

// ---------------- one-time weight split: fp32 [k][n] -> packed bf16 hi/lo [n][k2] ----------------
__global__ __launch_bounds__(256) void split_weights(P p){
  int mat = blockIdx.z;
  size_t HH = (size_t)HID*HID;
  const float* Wm;
  switch(mat){
    case 0: Wm=p.Whr;    break; case 1: Wm=p.Whu;    break; case 2:  Wm=p.Whc;    break;
    case 3: Wm=p.Whr+HH; break; case 4: Wm=p.Whu+HH; break; case 5:  Wm=p.Whc+HH; break;
    case 6: Wm=p.Wir+HH; break; case 7: Wm=p.Wiu+HH; break; case 8:  Wm=p.Wic+HH; break;
    case 9: Wm=p.Wir;    break; case 10:Wm=p.Wiu;    break; default: Wm=p.Wic;    break;
  }
  __shared__ float tile[32][33];
  int kc = blockIdx.y*32, n0 = blockIdx.x*32;
  int t = threadIdx.x;
  #pragma unroll
  for (int i=0;i<4;i++){
    int idx = t + i*256; int ky = idx>>5, nx = idx&31;
    tile[ky][nx] = Wm[(size_t)(kc+ky)*HID + n0+nx];
  }
  __syncthreads();
  #pragma unroll
  for (int i=0;i<2;i++){
    int slot = t + i*256; int ny = slot>>4, kx2 = slot&15;
    uint32_t hi, lo;
    split2(tile[kx2*2][ny], tile[kx2*2+1][ny], hi, lo);
    g_wsp[mat][0][n0+ny][(kc>>1)+kx2] = hi;
    g_wsp[mat][1][n0+ny][(kc>>1)+kx2] = lo;
  }
}

// ---------------- embed + scale -> split packed ----------------
__global__ void embed_split(P p){
  int idx = blockIdx.x*blockDim.x + threadIdx.x;
  if (idx >= NROW*(EMBD/4)) return;
  int row = idx/(EMBD/4), e4 = idx%(EMBD/4);
  float4 v = ((const float4*)p.emb)[(size_t)p.tok[row]*(EMBD/4)+e4];
  float s = sqrtf((float)EMBD);
  uint32_t h0,l0,h1,l1;
  split2(v.x*s, v.y*s, h0, l0);
  split2(v.z*s, v.w*s, h1, l1);
  g_x0sp[0][row][e4*2]   = h0; g_x0sp[0][row][e4*2+1] = h1;
  g_x0sp[1][row][e4*2]   = l0; g_x0sp[1][row][e4*2+1] = l1;
}

__global__ void init_h_kernel(P p){
  int i = blockIdx.x*blockDim.x + threadIdx.x;
  if (i >= NLAYERS*BH/2) return;
  int e = i*2;
  float v0 = p.hidden[e], v1 = p.hidden[e+1];
  g_hbuf[0][e] = v0; g_hbuf[0][e+1] = v1;
  int layer = e / BH, rem = e % BH;
  int r = rem / HID, k = rem % HID;
  uint32_t hi, lo; split2(v0, v1, hi, lo);
  g_hsp[0][layer][0][r][k>>1] = hi;
  g_hsp[0][layer][1][r][k>>1] = lo;
}
__global__ void copy_h_kernel(float* out){
  int i = blockIdx.x*blockDim.x + threadIdx.x;
  if (i < NLAYERS*BH) out[i] = g_hbuf[0][i];
}

// ---------------- recurrent triple-GEMM core (split-bf16, 3 MMA passes) ----------------
// acc[j] = A[32,1536] @ Wmat0+j[1536, n0:n0+32]; A pre-split packed, W pre-split packed.
__device__ __forceinline__ void rec_core(
    const uint32_t* __restrict__ Ahi, const uint32_t* __restrict__ Alo,
    int mat0, int n0, float acc[3][2][4])
{
  __shared__ uint32_t sA[2][32][20];
  __shared__ uint32_t sW[3][2][32][20];
  int t = threadIdx.x, warp = t>>5, lane = t&31;
  int gid = lane>>2, tig = lane&3;
  int rw = t>>2, q4 = t&3;

  #pragma unroll
  for (int j=0;j<3;j++)
    #pragma unroll
    for (int mt=0;mt<2;mt++)
      #pragma unroll
      for (int f=0;f<4;f++) acc[j][mt][f]=0.f;

  uint4 pa[2], pw[3][2];
  auto ld = [&](int kc2){
    pa[0] = *(const uint4*)&Ahi[rw*KH + kc2 + q4*4];
    pa[1] = *(const uint4*)&Alo[rw*KH + kc2 + q4*4];
    #pragma unroll
    for (int j=0;j<3;j++){
      pw[j][0] = *(const uint4*)&g_wsp[mat0+j][0][n0+rw][kc2 + q4*4];
      pw[j][1] = *(const uint4*)&g_wsp[mat0+j][1][n0+rw][kc2 + q4*4];
    }
  };
  ld(0);

  for (int kc2=0; kc2<KH; kc2+=16){
    *(uint4*)&sA[0][rw][q4*4] = pa[0];
    *(uint4*)&sA[1][rw][q4*4] = pa[1];
    #pragma unroll
    for (int j=0;j<3;j++){
      *(uint4*)&sW[j][0][rw][q4*4] = pw[j][0];
      *(uint4*)&sW[j][1][rw][q4*4] = pw[j][1];
    }
    __syncthreads();
    if (kc2+16 < KH) ld(kc2+16);
    int c = warp*8 + gid;
    #pragma unroll
    for (int ks=0; ks<2; ks++){
      int o = ks*8;
      uint32_t ah[2][4], al[2][4];
      #pragma unroll
      for (int mt=0;mt<2;mt++){
        int r = mt*16+gid;
        ah[mt][0]=sA[0][r  ][o+tig];   ah[mt][1]=sA[0][r+8][o+tig];
        ah[mt][2]=sA[0][r  ][o+4+tig]; ah[mt][3]=sA[0][r+8][o+4+tig];
        al[mt][0]=sA[1][r  ][o+tig];   al[mt][1]=sA[1][r+8][o+tig];
        al[mt][2]=sA[1][r  ][o+4+tig]; al[mt][3]=sA[1][r+8][o+4+tig];
      }
      #pragma unroll
      for (int j=0;j<3;j++){
        uint32_t bh0=sW[j][0][c][o+tig], bh1=sW[j][0][c][o+4+tig];
        uint32_t bl0=sW[j][1][c][o+tig], bl1=sW[j][1][c][o+4+tig];
        #pragma unroll
        for (int mt=0;mt<2;mt++){
          mma_bf16(acc[j][mt], ah[mt][0],ah[mt][1],ah[mt][2],ah[mt][3], bl0,bl1);
          mma_bf16(acc[j][mt], al[mt][0],al[mt][1],al[mt][2],al[mt][3], bh0,bh1);
          mma_bf16(acc[j][mt], ah[mt][0],ah[mt][1],ah[mt][2],ah[mt][3], bh0,bh1);
        }
      }
    }
    __syncthreads();
  }
}

// ---- step kernel 1: h-side GEMMs of both layers; layer-0 gates fused ----
__global__ __launch_bounds__(128) void rec_step1(P p, int t, int cb){
  int layer = blockIdx.y;
  int nb = cb^1;
  int n0 = blockIdx.x*32;
  float acc[3][2][4];
  rec_core(&g_hsp[cb][layer][0][0][0], &g_hsp[cb][layer][1][0][0],
           layer==0 ? 0 : 3, n0, acc);

  int lane = threadIdx.x&31, warp = threadIdx.x>>5;
  int gid = lane>>2, tig = lane&3;
  int cc = n0 + warp*8 + tig*2;

  if (layer==1){
    #pragma unroll
    for (int j=0;j<3;j++)
      #pragma unroll
      for (int mt=0;mt<2;mt++){
        int r = mt*16+gid;
        g_pre[(size_t)j*BH + (size_t)r*HID + cc]       = acc[j][mt][0];
        g_pre[(size_t)j*BH + (size_t)r*HID + cc+1]     = acc[j][mt][1];
        g_pre[(size_t)j*BH + (size_t)(r+8)*HID + cc]   = acc[j][mt][2];
        g_pre[(size_t)j*BH + (size_t)(r+8)*HID + cc+1] = acc[j][mt][3];
      }
  } else {
    #pragma unroll
    for (int mt=0;mt<2;mt++)
      #pragma unroll
      for (int half=0; half<2; half++){
        int r = mt*16+gid + half*8;
        size_t trow = (size_t)t*BATCH + r;
        float hn[2];
        #pragma unroll
        for (int e=0;e<2;e++){
          int f = half*2+e, col = cc+e;
          float xr = g_l0x[0*(size_t)NROW*HID + trow*HID + col];
          float xu = g_l0x[1*(size_t)NROW*HID + trow*HID + col];
          float xc = g_l0x[2*(size_t)NROW*HID + trow*HID + col];
          float rr = sigf(xr + p.bir[col] + acc[0][mt][f] + p.bhr[col]);
          float uu = sigf(xu + p.biu[col] + acc[1][mt][f] + p.bhu[col]);
          float cv = tanhf(xc + p.bic[col] + rr*(acc[2][mt][f] + p.bhc[col]));
          float h  = g_hbuf[cb][(size_t)r*HID + col];
          hn[e] = (1.f-uu)*cv + uu*h;
          g_hbuf[nb][(size_t)r*HID + col] = hn[e];
        }
        uint32_t hi, lo; split2(hn[0], hn[1], hi, lo);
        g_hsp[nb][0][0][r][cc>>1] = hi;
        g_hsp[nb][0][1][r][cc>>1] = lo;
      }
  }
}

// ---- step kernel 2: layer-1 x-side GEMMs (A = fresh h0) + layer-1 gates fused ----
__global__ __launch_bounds__(128) void rec_step2(P p, int t, int cb){
  int nb = cb^1;
  int n0 = blockIdx.x*32;
  float acc[3][2][4];
  rec_core(&g_hsp[nb][0][0][0][0], &g_hsp[nb][0][1][0][0], 6, n0, acc);

  int lane = threadIdx.x&31, warp = threadIdx.x>>5;
  int gid = lane>>2, tig = lane&3;
  int cc = n0 + warp*8 + tig*2;

  #pragma unroll
  for (int mt=0;mt<2;mt++)
    #pragma unroll
    for (int half=0; half<2; half++){
      int r = mt*16+gid + half*8;
      size_t trow = (size_t)t*BATCH + r;
      float hn[2];
      #pragma unroll
      for (int e=0;e<2;e++){
        int f = half*2+e, col = cc+e;
        float hr = g_pre[0*(size_t)BH + (size_t)r*HID + col];
        float hu = g_pre[1*(size_t)BH + (size_t)r*HID + col];
        float hc = g_pre[2*(size_t)BH + (size_t)r*HID + col];
        float rr = sigf(acc[0][mt][f] + p.bir[HID+col] + hr + p.bhr[HID+col]);
        float uu = sigf(acc[1][mt][f] + p.biu[HID+col] + hu + p.bhu[HID+col]);
        float cv = tanhf(acc[2][mt][f] + p.bic[HID+col] + rr*(hc + p.bhc[HID+col]));
        float h  = g_hbuf[cb][BH + (size_t)r*HID + col];
        hn[e] = (1.f-uu)*cv + uu*h;
        g_hbuf[nb][BH + (size_t)r*HID + col] = hn[e];
        g_X[trow*HID + col] = hn[e];
      }
      uint32_t hi, lo; split2(hn[0], hn[1], hi, lo);
      g_hsp[nb][1][0][r][cc>>1] = hi;
      g_hsp[nb][1][1][r][cc>>1] = lo;
    }
}

// ---------------- l0x GEMM (split-bf16): g_l0x[j] = x0 @ Wi{r,u,c}[0] ----------------
__global__ __launch_bounds__(256) void xproj_gemm(){
  int j = blockIdx.z; int mat = 9+j;
  int m0 = blockIdx.y*128, n0 = blockIdx.x*128;
  __shared__ uint32_t sA[2][128][20];
  __shared__ uint32_t sW[2][128][20];
  int t = threadIdx.x, warp = t>>5, lane = t&31;
  int gid = lane>>2, tig = lane&3;
  int wr = warp>>1, wc = warp&1;

  float acc[2][8][4];
  #pragma unroll
  for (int a=0;a<2;a++)
    #pragma unroll
    for (int b=0;b<8;b++)
      #pragma unroll
      for (int f=0;f<4;f++) acc[a][b][f]=0.f;

  uint4 pa[2][2], pw[2][2];
  auto ld = [&](int kc2){
    #pragma unroll
    for (int i=0;i<2;i++){
      int idx = t + i*256; int row = idx>>2, q4 = idx&3;
      pa[i][0] = *(const uint4*)&g_x0sp[0][m0+row][kc2+q4*4];
      pa[i][1] = *(const uint4*)&g_x0sp[1][m0+row][kc2+q4*4];
      pw[i][0] = *(const uint4*)&g_wsp[mat][0][n0+row][kc2+q4*4];
      pw[i][1] = *(const uint4*)&g_wsp[mat][1][n0+row][kc2+q4*4];
    }
  };
  ld(0);

  for (int kc2=0; kc2<KH; kc2+=16){
    #pragma unroll
    for (int i=0;i<2;i++){
      int idx = t + i*256; int row = idx>>2, q4 = idx&3;
      *(uint4*)&sA[0][row][q4*4] = pa[i][0];
      *(uint4*)&sA[1][row][q4*4] = pa[i][1];
      *(uint4*)&sW[0][row][q4*4] = pw[i][0];
      *(uint4*)&sW[1][row][q4*4] = pw[i][1];
    }
    __syncthreads();
    if (kc2+16 < KH) ld(kc2+16);
    #pragma unroll
    for (int ks=0; ks<2; ks++){
      int o = ks*8;
      uint32_t ah[2][4], al[2][4];
      #pragma unroll
      for (int mt=0;mt<2;mt++){
        int r = wr*32+mt*16+gid;
        ah[mt][0]=sA[0][r  ][o+tig];   ah[mt][1]=sA[0][r+8][o+tig];
        ah[mt][2]=sA[0][r  ][o+4+tig]; ah[mt][3]=sA[0][r+8][o+4+tig];
        al[mt][0]=sA[1][r  ][o+tig];   al[mt][1]=sA[1][r+8][o+tig];
        al[mt][2]=sA[1][r  ][o+4+tig]; al[mt][3]=sA[1][r+8][o+4+tig];
      }
      #pragma unroll
      for (int nt=0;nt<8;nt++){
        int c = wc*64+nt*8+gid;
        uint32_t bh0=sW[0][c][o+tig], bh1=sW[0][c][o+4+tig];
        uint32_t bl0=sW[1][c][o+tig], bl1=sW[1][c][o+4+tig];
        #pragma unroll
        for (int mt=0;mt<2;mt++){
          mma_bf16(acc[mt][nt], ah[mt][0],ah[mt][1],ah[mt][2],ah[mt][3], bl0,bl1);
          mma_bf16(acc[mt][nt], al[mt][0],al[mt][1],al[mt][2],al[mt][3], bh0,bh1);
          mma_bf16(acc[mt][nt], ah[mt][0],ah[mt][1],ah[mt][2],ah[mt][3], bh0,bh1);
        }
      }
    }
    __syncthreads();
  }
  float* C = g_l0x + (size_t)j*NROW*HID;
  #pragma unroll
  for (int mt=0;mt<2;mt++){
    int r0 = m0 + wr*32 + mt*16 + gid;
    #pragma unroll
    for (int nt=0;nt<8;nt++){
      int col = n0 + wc*64 + nt*8 + tig*2;
      C[(size_t)r0*HID + col  ]     = acc[mt][nt][0];
      C[(size_t)r0*HID + col+1]     = acc[mt][nt][1];
      C[(size_t)(r0+8)*HID + col  ] = acc[mt][nt][2];
      C[(size_t)(r0+8)*HID + col+1] = acc[mt][nt][3];
    }
  }
}

// ---------------- output GEMM (single-pass TF32): logits = X @ Wout + bout ----------------
__global__ __launch_bounds__(256) void out_gemm(
    const float* __restrict__ A, const float* __restrict__ W,
    float* __restrict__ C, const float* __restrict__ bias, int N)
{
  constexpr int BK = 16;
  __shared__ float As[128][BK+4];
  __shared__ float Ws[BK][128+8];

  int tid = threadIdx.x;
  int warp = tid>>5, lane = tid&31;
  int gid = lane>>2, tig = lane&3;
  int wr = warp>>1, wc = warp&1;
  int m0 = blockIdx.y*128, n0 = blockIdx.x*128;

  float acc[2][8][4];
  #pragma unroll
  for (int a=0;a<2;a++)
    #pragma unroll
    for (int b=0;b<8;b++)
      #pragma unroll
      for (int cc=0;cc<4;cc++) acc[a][b][cc]=0.f;

  float4 ra[2], rw[2];
  auto loadA = [&](int kc){
    #pragma unroll
    for (int i=0;i<2;i++){
      int q = tid + i*256; int m = q>>2, k4 = q&3;
      ra[i] = *(const float4*)(A + (size_t)(m0+m)*HID + kc + k4*4);
    }
  };
  auto loadW = [&](int kc){
    #pragma unroll
    for (int i=0;i<2;i++){
      int q = tid + i*256; int k = q>>5, n4 = q&31;
      rw[i] = *(const float4*)(W + (size_t)(kc+k)*N + n0 + n4*4);
    }
  };
  loadA(0); loadW(0);

  for (int kc=0; kc<HID; kc+=BK){
    #pragma unroll
    for (int i=0;i<2;i++){
      int q = tid + i*256; int m = q>>2, k4 = q&3;
      float vv[4] = {ra[i].x,ra[i].y,ra[i].z,ra[i].w};
      #pragma unroll
      for (int j=0;j<4;j++) As[m][k4*4+j] = tf32_rna(vv[j]);
    }
    #pragma unroll
    for (int i=0;i<2;i++){
      int q = tid + i*256; int k = q>>5, n4 = q&31;
      float vv[4] = {rw[i].x,rw[i].y,rw[i].z,rw[i].w};
      #pragma unroll
      for (int j=0;j<4;j++) Ws[k][n4*4+j] = tf32_rna(vv[j]);
    }
    __syncthreads();
    if (kc+BK < HID){ loadA(kc+BK); loadW(kc+BK); }

    #pragma unroll
    for (int ks=0; ks<BK/8; ks++){
      int kk = ks*8;
      uint32_t ah[2][4];
      #pragma unroll
      for (int mt=0; mt<2; mt++){
        int ar = wr*32 + mt*16 + gid;
        ah[mt][0]=__float_as_uint(As[ar  ][kk+tig  ]);
        ah[mt][1]=__float_as_uint(As[ar+8][kk+tig  ]);
        ah[mt][2]=__float_as_uint(As[ar  ][kk+tig+4]);
        ah[mt][3]=__float_as_uint(As[ar+8][kk+tig+4]);
      }
      #pragma unroll
      for (int nt=0; nt<8; nt++){
        int c = wc*64 + nt*8 + gid;
        uint32_t bh0=__float_as_uint(Ws[kk+tig  ][c]);
        uint32_t bh1=__float_as_uint(Ws[kk+tig+4][c]);
        #pragma unroll
        for (int mt=0; mt<2; mt++)
          mma_tf32(acc[mt][nt], ah[mt][0],ah[mt][1],ah[mt][2],ah[mt][3], bh0,bh1);
      }
    }
    __syncthreads();
  }
  #pragma unroll
  for (int mt=0; mt<2; mt++){
    int r0 = m0 + wr*32 + mt*16 + gid;
    #pragma unroll
    for (int nt=0; nt<8; nt++){
      int col = n0 + wc*64 + nt*8 + tig*2;
      float b0 = bias[col], b1 = bias[col+1];
      C[(size_t)r0*N + col  ]     = acc[mt][nt][0] + b0;
      C[(size_t)r0*N + col+1]     = acc[mt][nt][1] + b1;
      C[(size_t)(r0+8)*N + col  ] = acc[mt][nt][2] + b0;
      C[(size_t)(r0+8)*N + col+1] = acc[mt][nt][3] + b1;
    }
  }
}

extern "C" void kernel_launch(void* const* d_in, const int* in_sizes, int n_in,
                              void* d_out, int out_size) {
  P p;
  p.tok = (const int*)  d_in[0];
  p.hidden = (const float*)d_in[1];
  p.emb = (const float*)d_in[2];
  p.Wir = (const float*)d_in[3];  p.bir = (const float*)d_in[4];
  p.Whr = (const float*)d_in[5];  p.bhr = (const float*)d_in[6];
  p.Wiu = (const float*)d_in[7];  p.biu = (const float*)d_in[8];
  p.Whu = (const float*)d_in[9];  p.bhu = (const float*)d_in[10];
  p.Wic = (const float*)d_in[11]; p.bic = (const float*)d_in[12];
  p.Whc = (const float*)d_in[13]; p.bhc = (const float*)d_in[14];
  p.Wout= (const float*)d_in[15]; p.bout= (const float*)d_in[16];
  float* out = (float*)d_out;

  float* X; cudaGetSymbolAddress((void**)&X, g_X);

  split_weights<<<dim3(HID/32, HID/32, 12), 256>>>(p);
  init_h_kernel<<<(NLAYERS*BH/2+255)/256, 256>>>(p);
  embed_split<<<(NROW*(EMBD/4)+255)/256, 256>>>(p);

  xproj_gemm<<<dim3(HID/128, NROW/128, 3), 256>>>();

  for (int t=0; t<SEQ; t++){
    rec_step1<<<dim3(HID/32, 2), 128>>>(p, t, t&1);
    rec_step2<<<dim3(HID/32),    128>>>(p, t, t&1);
  }

  out_gemm<<<dim3(VOCAB/128, NROW/128), 256>>>(X, p.Wout, out, p.bout, VOCAB);
  copy_h_kernel<<<(NLAYERS*BH+255)/256, 256>>>(out + (size_t)SEQ*BATCH*VOCAB);
}